// round 2
// baseline (speedup 1.0000x reference)
#include <cuda_runtime.h>
#include <cuda_bf16.h>
#include <cstddef>
#include <cstdint>

#define DIMN   512
#define NSLOT  32
#define BATCH  32
#define TSTEPS 2048

// ---------------- scratch (static __device__ allocations only) ----------------
__device__ float g_pre[(size_t)BATCH * TSTEPS * DIMN];   // 128 MiB: x@Wx^T + b_h
__device__ float g_WhP[DIMN * DIMN];                     // packed W_h  [k/4][d][4]
__device__ float g_WwP[DIMN * DIMN];                     // packed W_write

// ---------------- weight packing ----------------
// packed[(k>>2)*DIMN*4 + d*4 + (k&3)] = W[d*DIMN + k]
// so a float4 load at index (k4*DIMN + d) gives W[4k4..4k4+3][d]
__global__ void pack_weights(const float* __restrict__ Wh,
                             const float* __restrict__ Ww) {
    int idx = blockIdx.x * blockDim.x + threadIdx.x;
    if (idx >= DIMN * DIMN) return;
    int d = idx / DIMN;
    int k = idx % DIMN;
    int dst = ((k >> 2) * DIMN + d) * 4 + (k & 3);
    g_WhP[dst] = Wh[idx];
    g_WwP[dst] = Ww[idx];
}

// ---------------- pre-GEMM: pre[m][n] = sum_k X[m][k] * W[n][k] + b[n] ----------------
// Tiles: BM=128, BN=64, BK=8, 256 threads, 8x4 per-thread microtile.
__global__ __launch_bounds__(256) void gemm_pre(
    const float* __restrict__ X,     // [M, 512]
    const float* __restrict__ W,     // [512, 512] (row n, col k)
    const float* __restrict__ bias)  // [512]
{
    __shared__ float As[8][128];
    __shared__ float Bs[8][64];

    const int tid = threadIdx.x;
    const int m0 = blockIdx.y * 128;
    const int n0 = blockIdx.x * 64;
    const int trow = tid >> 4;   // 0..15 -> 8 rows each
    const int tcol = tid & 15;   // 0..15 -> 4 cols each

    float acc[8][4];
#pragma unroll
    for (int i = 0; i < 8; ++i)
#pragma unroll
        for (int j = 0; j < 4; ++j) acc[i][j] = 0.f;

    const int a_m  = tid >> 1;          // 0..127
    const int a_k4 = (tid & 1) * 4;     // 0 or 4

    for (int k0 = 0; k0 < DIMN; k0 += 8) {
        // A tile 128x8 (store transposed)
        float4 av = *reinterpret_cast<const float4*>(
            X + (size_t)(m0 + a_m) * DIMN + k0 + a_k4);
        As[a_k4 + 0][a_m] = av.x;
        As[a_k4 + 1][a_m] = av.y;
        As[a_k4 + 2][a_m] = av.z;
        As[a_k4 + 3][a_m] = av.w;
        // B tile 64x8 (store transposed): B[k][n] = W[n][k]
        if (tid < 128) {
            int bn  = tid >> 1;
            int bk4 = (tid & 1) * 4;
            float4 bv = *reinterpret_cast<const float4*>(
                W + (size_t)(n0 + bn) * DIMN + k0 + bk4);
            Bs[bk4 + 0][bn] = bv.x;
            Bs[bk4 + 1][bn] = bv.y;
            Bs[bk4 + 2][bn] = bv.z;
            Bs[bk4 + 3][bn] = bv.w;
        }
        __syncthreads();
#pragma unroll
        for (int kk = 0; kk < 8; ++kk) {
            float4 ra0 = *reinterpret_cast<const float4*>(&As[kk][trow * 8]);
            float4 ra1 = *reinterpret_cast<const float4*>(&As[kk][trow * 8 + 4]);
            float4 rb  = *reinterpret_cast<const float4*>(&Bs[kk][tcol * 4]);
            float ra[8] = {ra0.x, ra0.y, ra0.z, ra0.w, ra1.x, ra1.y, ra1.z, ra1.w};
            float rbv[4] = {rb.x, rb.y, rb.z, rb.w};
#pragma unroll
            for (int i = 0; i < 8; ++i)
#pragma unroll
                for (int j = 0; j < 4; ++j) acc[i][j] += ra[i] * rbv[j];
        }
        __syncthreads();
    }

    float4 bj = *reinterpret_cast<const float4*>(bias + n0 + tcol * 4);
#pragma unroll
    for (int i = 0; i < 8; ++i) {
        float4 v;
        v.x = acc[i][0] + bj.x;
        v.y = acc[i][1] + bj.y;
        v.z = acc[i][2] + bj.z;
        v.w = acc[i][3] + bj.w;
        *reinterpret_cast<float4*>(
            &g_pre[(size_t)(m0 + trow * 8 + i) * DIMN + n0 + tcol * 4]) = v;
    }
}

// ---------------- exact entmax-1.5 over 32 values, one warp ----------------
__device__ __forceinline__ void entmax_warp(const float* __restrict__ scores,
                                            float* __restrict__ coef,
                                            float* __restrict__ sortb,
                                            int lane) {
    const unsigned FULL = 0xffffffffu;
    float z = scores[lane] * 0.5f;
    float m = z;
#pragma unroll
    for (int o = 16; o > 0; o >>= 1) m = fmaxf(m, __shfl_xor_sync(FULL, m, o));
    z -= m;

    // rank (descending, stable) via all-pairs comparison
    int rank = 0;
#pragma unroll
    for (int j = 0; j < 32; ++j) {
        float zj = __shfl_sync(FULL, z, j);
        rank += (zj > z) || (zj == z && j < lane);
    }
    sortb[rank] = z;
    __syncwarp();
    float zs = sortb[lane];      // lane r holds r-th largest

    // inclusive prefix sums of zs and zs^2
    float cs = zs, cq = zs * zs;
#pragma unroll
    for (int o = 1; o < 32; o <<= 1) {
        float a  = __shfl_up_sync(FULL, cs, o);
        float bq = __shfl_up_sync(FULL, cq, o);
        if (lane >= o) { cs += a; cq += bq; }
    }
    float k    = (float)(lane + 1);
    float mean = cs / k;
    float msq  = cq / k;
    float ss   = k * (msq - mean * mean);
    float delta = fmaxf((1.f - ss) / k, 0.f);
    float tau   = mean - sqrtf(delta);

    unsigned sup = __ballot_sync(FULL, tau <= zs);
    int kstar = __popc(sup) - 1;
    float tau_star = __shfl_sync(FULL, tau, kstar);
    float p = fmaxf(z - tau_star, 0.f);
    coef[lane] = p * p;
}

// ---------------- persistent recurrence: 1 CTA per batch ----------------
__global__ __launch_bounds__(512) void recur(
    const float* __restrict__ tape0,   // [B, N, D]
    const float* __restrict__ work0,   // [B, D]
    float* __restrict__ out_hseq,      // [B, T, D]
    float* __restrict__ out_tape,      // [B, N, D]
    float* __restrict__ out_hlast)     // [B, D]
{
    extern __shared__ float sm[];
    float* tape   = sm;                      // 32*512
    float* work   = sm + NSLOT * DIMN;       // 512
    float* wnew   = work + DIMN;             // 512
    float* wvec   = wnew + DIMN;             // 512
    float* scores = wvec + DIMN;             // 32
    float* coef   = scores + NSLOT;          // 32
    float* sortb  = coef + NSLOT;            // 32

    const int b    = blockIdx.x;
    const int tid  = threadIdx.x;
    const int lane = tid & 31;
    const int wid  = tid >> 5;

    // init state
    {
        const float* tp = tape0 + (size_t)b * NSLOT * DIMN;
        for (int i = tid; i < NSLOT * DIMN; i += 512) tape[i] = tp[i];
        work[tid] = work0[(size_t)b * DIMN + tid];
    }
    __syncthreads();

    const float inv_sqrt_d = 0.044194173824159216f;  // 1/sqrt(512)
    float* hseq_b = out_hseq + (size_t)b * TSTEPS * DIMN;
    const float* pre_b = g_pre + (size_t)b * TSTEPS * DIMN;

    for (int t = 0; t < TSTEPS; ++t) {
        float pre_v = __ldcs(pre_b + (size_t)t * DIMN + tid);  // prefetch

        // phase 1: r_scores[n] = tape[n,:].work / sqrt(D)
#pragma unroll
        for (int s = 0; s < 2; ++s) {
            int n = wid * 2 + s;
            const float4* tp4 = reinterpret_cast<const float4*>(tape + n * DIMN);
            const float4* wk4 = reinterpret_cast<const float4*>(work);
            float acc = 0.f;
#pragma unroll
            for (int i = 0; i < 4; ++i) {
                float4 a = tp4[lane + 32 * i];
                float4 c = wk4[lane + 32 * i];
                acc += a.x * c.x + a.y * c.y + a.z * c.z + a.w * c.w;
            }
#pragma unroll
            for (int o = 16; o > 0; o >>= 1) acc += __shfl_xor_sync(0xffffffffu, acc, o);
            if (lane == 0) scores[n] = acc * inv_sqrt_d;
        }
        __syncthreads();

        // phase 2: alpha = entmax15(r_scores)
        if (wid == 0) entmax_warp(scores, coef, sortb, lane);
        __syncthreads();

        // phase 3: work_new = tanh(W_h.work + pre + read)
        {
            const int d = tid;
            float acc = pre_v;
#pragma unroll 8
            for (int n = 0; n < NSLOT; ++n) acc += coef[n] * tape[n * DIMN + d];
            const float4* Wp  = reinterpret_cast<const float4*>(g_WhP);
            const float4* wk4 = reinterpret_cast<const float4*>(work);
#pragma unroll 8
            for (int k4 = 0; k4 < DIMN / 4; ++k4) {
                float4 wm = Wp[(size_t)k4 * DIMN + d];
                float4 wv = wk4[k4];
                acc += wm.x * wv.x + wm.y * wv.y + wm.z * wv.z + wm.w * wv.w;
            }
            float h = tanhf(acc);
            wnew[d] = h;
            __stcs(hseq_b + (size_t)t * DIMN + d, h);
        }
        __syncthreads();

        // phase 4: w_vec = W_write . work_new
        {
            const int d = tid;
            float acc = 0.f;
            const float4* Wp  = reinterpret_cast<const float4*>(g_WwP);
            const float4* wk4 = reinterpret_cast<const float4*>(wnew);
#pragma unroll 8
            for (int k4 = 0; k4 < DIMN / 4; ++k4) {
                float4 wm = Wp[(size_t)k4 * DIMN + d];
                float4 wv = wk4[k4];
                acc += wm.x * wv.x + wm.y * wv.y + wm.z * wv.z + wm.w * wv.w;
            }
            wvec[d] = acc;
        }
        __syncthreads();

        // phase 5: w_scores[n] = tape[n,:].w_vec / sqrt(D)
#pragma unroll
        for (int s = 0; s < 2; ++s) {
            int n = wid * 2 + s;
            const float4* tp4 = reinterpret_cast<const float4*>(tape + n * DIMN);
            const float4* wk4 = reinterpret_cast<const float4*>(wvec);
            float acc = 0.f;
#pragma unroll
            for (int i = 0; i < 4; ++i) {
                float4 a = tp4[lane + 32 * i];
                float4 c = wk4[lane + 32 * i];
                acc += a.x * c.x + a.y * c.y + a.z * c.z + a.w * c.w;
            }
#pragma unroll
            for (int o = 16; o > 0; o >>= 1) acc += __shfl_xor_sync(0xffffffffu, acc, o);
            if (lane == 0) scores[n] = acc * inv_sqrt_d;
        }
        __syncthreads();

        // phase 6: beta = entmax15(w_scores)
        if (wid == 0) entmax_warp(scores, coef, sortb, lane);
        __syncthreads();

        // phase 7: tape convex update + commit work
        {
            const int d = tid;
            float wv = wvec[d];
#pragma unroll 8
            for (int n = 0; n < NSLOT; ++n) {
                float bta = coef[n];
                tape[n * DIMN + d] = tape[n * DIMN + d] * (1.f - bta) + bta * wv;
            }
            work[d] = wnew[d];
        }
        __syncthreads();
    }

    // final outputs
    {
        float* tp = out_tape + (size_t)b * NSLOT * DIMN;
        for (int i = tid; i < NSLOT * DIMN; i += 512) tp[i] = tape[i];
        out_hlast[(size_t)b * DIMN + tid] = work[tid];
    }
}

// ---------------- launch ----------------
extern "C" void kernel_launch(void* const* d_in, const int* in_sizes, int n_in,
                              void* d_out, int out_size) {
    const float* x     = (const float*)d_in[0];  // [B,T,D]
    const float* tape0 = (const float*)d_in[1];  // [B,N,D]
    const float* work0 = (const float*)d_in[2];  // [B,D]
    const float* Wh    = (const float*)d_in[3];  // [D,D]
    const float* Wx    = (const float*)d_in[4];  // [D,D]
    const float* bh    = (const float*)d_in[5];  // [D]
    const float* Ww    = (const float*)d_in[6];  // [D,D]

    float* out       = (float*)d_out;
    float* out_hseq  = out;
    float* out_tape  = out + (size_t)BATCH * TSTEPS * DIMN;
    float* out_hlast = out_tape + (size_t)BATCH * NSLOT * DIMN;

    pack_weights<<<(DIMN * DIMN + 511) / 512, 512>>>(Wh, Ww);

    dim3 ggrid(DIMN / 64, (BATCH * TSTEPS) / 128);
    gemm_pre<<<ggrid, 256>>>(x, Wx, bh);

    const int smem_bytes = (NSLOT * DIMN + 3 * DIMN + 3 * NSLOT) * (int)sizeof(float);
    cudaFuncSetAttribute(recur, cudaFuncAttributeMaxDynamicSharedMemorySize, smem_bytes);
    recur<<<BATCH, DIMN, smem_bytes>>>(tape0, work0, out_hseq, out_tape, out_hlast);
}

// round 3
// speedup vs baseline: 1.4289x; 1.4289x over previous
#include <cuda_runtime.h>
#include <cuda_bf16.h>
#include <cstddef>
#include <cstdint>

#define DIMN   512
#define NSLOT  32
#define BATCH  32
#define TSTEPS 2048
#define RANKS  8      // d-chunks per cluster (cluster size)
#define BPC    4      // batches per CTA
#define DCH    64     // d columns per CTA

// ---------------- scratch (static __device__ allocations only) ----------------
__device__ float g_pre[(size_t)BATCH * TSTEPS * DIMN];   // x@Wx^T + b_h
__device__ float g_WhP[DIMN * DIMN];                     // packed W_h  [k/4][d][4]
__device__ float g_WwP[DIMN * DIMN];                     // packed W_write

// ---------------- PTX helpers ----------------
__device__ __forceinline__ uint32_t smem_u32(const void* p) {
    uint32_t a;
    asm("{ .reg .u64 t; cvta.to.shared.u64 t, %1; cvt.u32.u64 %0, t; }"
        : "=r"(a) : "l"(p));
    return a;
}
__device__ __forceinline__ uint32_t mapa_rank(uint32_t laddr, uint32_t rank) {
    uint32_t r;
    asm("mapa.shared::cluster.u32 %0, %1, %2;" : "=r"(r) : "r"(laddr), "r"(rank));
    return r;
}
__device__ __forceinline__ void sts_cluster_f32(uint32_t addr, float v) {
    asm volatile("st.shared::cluster.f32 [%0], %1;" :: "r"(addr), "f"(v) : "memory");
}
__device__ __forceinline__ void mbar_init(uint32_t addr, uint32_t cnt) {
    asm volatile("mbarrier.init.shared.b64 [%0], %1;" :: "r"(addr), "r"(cnt) : "memory");
}
__device__ __forceinline__ void mbar_arrive_cl(uint32_t remAddr) {
    asm volatile("mbarrier.arrive.release.cluster.shared::cluster.b64 _, [%0];"
                 :: "r"(remAddr) : "memory");
}
__device__ __forceinline__ void mbar_wait_parity_cl(uint32_t addr, uint32_t parity) {
    asm volatile(
        "{\n\t"
        ".reg .pred P;\n\t"
        "LAB_WAIT_%=:\n\t"
        "mbarrier.try_wait.parity.acquire.cluster.shared::cta.b64 P, [%0], %1, 0x989680;\n\t"
        "@P bra.uni LAB_DONE_%=;\n\t"
        "bra.uni LAB_WAIT_%=;\n\t"
        "LAB_DONE_%=:\n\t"
        "}"
        :: "r"(addr), "r"(parity) : "memory");
}
__device__ __forceinline__ void cluster_sync_() {
    asm volatile("barrier.cluster.arrive.aligned;\n\tbarrier.cluster.wait.aligned;" ::: "memory");
}

// ---------------- weight packing ----------------
// packed[(k>>2)*DIMN*4 + d*4 + (k&3)] = W[d*DIMN + k]
__global__ void pack_weights(const float* __restrict__ Wh,
                             const float* __restrict__ Ww) {
    int idx = blockIdx.x * blockDim.x + threadIdx.x;
    if (idx >= DIMN * DIMN) return;
    int d = idx / DIMN;
    int k = idx % DIMN;
    int dst = ((k >> 2) * DIMN + d) * 4 + (k & 3);
    g_WhP[dst] = Wh[idx];
    g_WwP[dst] = Ww[idx];
}

// ---------------- pre-GEMM: pre[m][n] = sum_k X[m][k] * W[n][k] + b[n] ----------------
__global__ __launch_bounds__(256) void gemm_pre(
    const float* __restrict__ X,
    const float* __restrict__ W,
    const float* __restrict__ bias)
{
    __shared__ float As[8][128];
    __shared__ float Bs[8][64];

    const int tid = threadIdx.x;
    const int m0 = blockIdx.y * 128;
    const int n0 = blockIdx.x * 64;
    const int trow = tid >> 4;
    const int tcol = tid & 15;

    float acc[8][4];
#pragma unroll
    for (int i = 0; i < 8; ++i)
#pragma unroll
        for (int j = 0; j < 4; ++j) acc[i][j] = 0.f;

    const int a_m  = tid >> 1;
    const int a_k4 = (tid & 1) * 4;

    for (int k0 = 0; k0 < DIMN; k0 += 8) {
        float4 av = *reinterpret_cast<const float4*>(
            X + (size_t)(m0 + a_m) * DIMN + k0 + a_k4);
        As[a_k4 + 0][a_m] = av.x;
        As[a_k4 + 1][a_m] = av.y;
        As[a_k4 + 2][a_m] = av.z;
        As[a_k4 + 3][a_m] = av.w;
        if (tid < 128) {
            int bn  = tid >> 1;
            int bk4 = (tid & 1) * 4;
            float4 bv = *reinterpret_cast<const float4*>(
                W + (size_t)(n0 + bn) * DIMN + k0 + bk4);
            Bs[bk4 + 0][bn] = bv.x;
            Bs[bk4 + 1][bn] = bv.y;
            Bs[bk4 + 2][bn] = bv.z;
            Bs[bk4 + 3][bn] = bv.w;
        }
        __syncthreads();
#pragma unroll
        for (int kk = 0; kk < 8; ++kk) {
            float4 ra0 = *reinterpret_cast<const float4*>(&As[kk][trow * 8]);
            float4 ra1 = *reinterpret_cast<const float4*>(&As[kk][trow * 8 + 4]);
            float4 rb  = *reinterpret_cast<const float4*>(&Bs[kk][tcol * 4]);
            float ra[8] = {ra0.x, ra0.y, ra0.z, ra0.w, ra1.x, ra1.y, ra1.z, ra1.w};
            float rbv[4] = {rb.x, rb.y, rb.z, rb.w};
#pragma unroll
            for (int i = 0; i < 8; ++i)
#pragma unroll
                for (int j = 0; j < 4; ++j) acc[i][j] += ra[i] * rbv[j];
        }
        __syncthreads();
    }

    float4 bj = *reinterpret_cast<const float4*>(bias + n0 + tcol * 4);
#pragma unroll
    for (int i = 0; i < 8; ++i) {
        float4 v;
        v.x = acc[i][0] + bj.x;
        v.y = acc[i][1] + bj.y;
        v.z = acc[i][2] + bj.z;
        v.w = acc[i][3] + bj.w;
        *reinterpret_cast<float4*>(
            &g_pre[(size_t)(m0 + trow * 8 + i) * DIMN + n0 + tcol * 4]) = v;
    }
}

// ---------------- exact entmax-1.5 coefficient for one of 32 values ----------------
__device__ __forceinline__ float entmax_coef(float raw, float* __restrict__ sb, int lane) {
    const unsigned FULL = 0xffffffffu;
    float z = raw * 0.5f;
    float m = z;
#pragma unroll
    for (int o = 16; o > 0; o >>= 1) m = fmaxf(m, __shfl_xor_sync(FULL, m, o));
    z -= m;

    int rank = 0;
#pragma unroll
    for (int j = 0; j < 32; ++j) {
        float zj = __shfl_sync(FULL, z, j);
        rank += (zj > z) || (zj == z && j < lane);
    }
    sb[rank] = z;
    __syncwarp();
    float zs = sb[lane];

    float cs = zs, cq = zs * zs;
#pragma unroll
    for (int o = 1; o < 32; o <<= 1) {
        float a  = __shfl_up_sync(FULL, cs, o);
        float bq = __shfl_up_sync(FULL, cq, o);
        if (lane >= o) { cs += a; cq += bq; }
    }
    float k    = (float)(lane + 1);
    float mean = cs / k;
    float msq  = cq / k;
    float ss   = k * (msq - mean * mean);
    float delta = fmaxf((1.f - ss) / k, 0.f);
    float tau   = mean - sqrtf(delta);

    unsigned sup = __ballot_sync(FULL, tau <= zs);
    int kstar = __popc(sup) - 1;
    float tau_star = __shfl_sync(FULL, tau, kstar);
    float p = fmaxf(z - tau_star, 0.f);
    return p * p;
}

// ---------------- GEMV partials: part[g][b][dl] over this CTA's 64 d ----------------
__device__ __forceinline__ void gemv_part(const float* __restrict__ Wp,
                                          const float* __restrict__ src,   // [8][4][64] floats
                                          float* __restrict__ part,
                                          int wid, int lane, int dbase) {
    int g  = wid >> 1;
    int dh = wid & 1;
    int dglob = dbase + dh * 32 + lane;
    const float4* W4 = reinterpret_cast<const float4*>(Wp) + (size_t)(g * 16) * DIMN + dglob;
    const float4* S4 = reinterpret_cast<const float4*>(src) + g * 64;  // slot g: [4][16]
    float a0 = 0.f, a1 = 0.f, a2 = 0.f, a3 = 0.f;
#pragma unroll
    for (int i = 0; i < 16; ++i) {
        float4 wm = __ldg(W4 + (size_t)i * DIMN);
        float4 k0 = S4[i];
        float4 k1 = S4[16 + i];
        float4 k2 = S4[32 + i];
        float4 k3 = S4[48 + i];
        a0 += wm.x * k0.x + wm.y * k0.y + wm.z * k0.z + wm.w * k0.w;
        a1 += wm.x * k1.x + wm.y * k1.y + wm.z * k1.z + wm.w * k1.w;
        a2 += wm.x * k2.x + wm.y * k2.y + wm.z * k2.z + wm.w * k2.w;
        a3 += wm.x * k3.x + wm.y * k3.y + wm.z * k3.z + wm.w * k3.w;
    }
    int dl = dh * 32 + lane;
    part[g * 256 +   0 + dl] = a0;
    part[g * 256 +  64 + dl] = a1;
    part[g * 256 + 128 + dl] = a2;
    part[g * 256 + 192 + dl] = a3;
}

// ---------------- partial scores + DSMEM push (warp handles batch b, lane = slot n) ----
__device__ __forceinline__ void scores_push(const float* __restrict__ tape,
                                            const float* __restrict__ wsrc,  // [64] for batch b
                                            int b, int lane,
                                            uint32_t a_dst, int p, int rank) {
    const float invsd = 0.044194173824159216f;  // 1/sqrt(512)
    float acc = 0.f;
    const float* tr = tape + (b * NSLOT + lane) * 65;
#pragma unroll 16
    for (int d = 0; d < 64; ++d) acc += tr[d] * wsrc[d];
    acc *= invsd;
    uint32_t off = ((unsigned)p * 1024u + (unsigned)rank * 128u + (unsigned)(b * 32 + lane)) * 4u;
#pragma unroll
    for (int peer = 0; peer < RANKS; ++peer)
        sts_cluster_f32(mapa_rank(a_dst + off, peer), acc);
}

// ---------------- persistent recurrence: cluster of 8 d-chunks, 4 batches per CTA ----
// SMEM float layout:
//   part  [8][4][64]        @ 0      (2048)
//   xwn   [2][8][4][64]     @ 2048   (4096)
//   xsc   [2][8][128]       @ 6144   (2048)
//   xws   [2][8][128]       @ 8192   (2048)
//   wvec  [4][64]           @ 10240  (256)
//   coef  [4][32]           @ 10496  (128)
//   sortb [4][32]           @ 10624  (128)
//   tape  [4][32][65]       @ 10752  (8320)
//   mbarriers (3 x u64)     @ 19072 floats (byte 76288)
__global__ void __launch_bounds__(512, 1) __cluster_dims__(RANKS, 1, 1)
recur2(const float* __restrict__ tape0,
       const float* __restrict__ work0,
       float* __restrict__ out_hseq,
       float* __restrict__ out_tape,
       float* __restrict__ out_hlast)
{
    extern __shared__ float sm[];
    float* part  = sm;
    float* xwn   = sm + 2048;
    float* xsc   = sm + 6144;
    float* xws   = sm + 8192;
    float* wvec  = sm + 10240;
    float* coef  = sm + 10496;
    float* sortb = sm + 10624;
    float* tape  = sm + 10752;

    const int tid  = threadIdx.x;
    const int lane = tid & 31;
    const int wid  = tid >> 5;
    const int rank = blockIdx.x & (RANKS - 1);   // d-chunk id == cluster rank
    const int bg   = blockIdx.x >> 3;            // batch group
    const int b0   = bg * BPC;
    const int dbase = rank * DCH;

    const uint32_t sbase = smem_u32(sm);
    const uint32_t a_xwn = sbase + 2048u * 4u;
    const uint32_t a_xsc = sbase + 6144u * 4u;
    const uint32_t a_xws = sbase + 8192u * 4u;
    const uint32_t a_mb  = sbase + 19072u * 4u;

    if (tid == 0) {
        mbar_init(a_mb + 0,  RANKS);
        mbar_init(a_mb + 8,  RANKS);
        mbar_init(a_mb + 16, RANKS);
    }

    // load tape slice [4 batches][32 slots][my 64 d]
    for (int i = tid; i < BPC * NSLOT * DCH; i += 512) {
        int b = i / (NSLOT * DCH);
        int r = i % (NSLOT * DCH);
        int n = r / DCH;
        int d = r % DCH;
        tape[(b * NSLOT + n) * 65 + d] =
            tape0[((size_t)(b0 + b) * NSLOT + n) * DIMN + dbase + d];
    }
    // init xwn[1] = full work0 for my 4 batches (all 8 slots from global)
    for (int i = tid; i < RANKS * BPC * DCH; i += 512) {
        int s = i / (BPC * DCH);
        int r = i % (BPC * DCH);
        int b = r / DCH;
        int d = r % DCH;
        xwn[2048 + i] = work0[(size_t)(b0 + b) * DIMN + s * DCH + d];
    }
    __syncthreads();
    cluster_sync_();

    for (int t = 0; t < TSTEPS; ++t) {
        const int p = t & 1;
        const float* xwn_old = xwn + (p ^ 1) * 2048;
        const float* xwn_new = xwn + p * 2048;

        // prefetch pre
        float pre_v = 0.f;
        if (tid < 256) {
            int b = tid >> 6, d = tid & 63;
            pre_v = __ldcs(&g_pre[((size_t)(b0 + b) * TSTEPS + t) * DIMN + dbase + d]);
        }

        // phase 1: partial read-scores, push to all CTAs
        if (wid < BPC)
            scores_push(tape, xwn_old + rank * 256 + wid * 64, wid, lane, a_xsc, p, rank);
        __syncthreads();
        if (tid == 0) {
#pragma unroll
            for (int peer = 0; peer < RANKS; ++peer)
                mbar_arrive_cl(mapa_rank(a_mb + 0, peer));
        }
        mbar_wait_parity_cl(a_mb + 0, (uint32_t)p);

        // phase 2: reduce partials + entmax (alpha)
        if (wid < BPC) {
            const float* base = xsc + p * 1024 + wid * 32 + lane;
            float s = 0.f;
#pragma unroll
            for (int sl = 0; sl < RANKS; ++sl) s += base[sl * 128];
            coef[wid * 32 + lane] = entmax_coef(s, sortb + wid * 32, lane);
        }
        __syncthreads();

        // phase 3: W_h GEMV partials, then reduce + read-term + tanh, push wnew
        gemv_part(g_WhP, xwn_old, part, wid, lane, dbase);
        __syncthreads();
        if (tid < 256) {
            int b = tid >> 6, d = tid & 63;
            float acc = pre_v;
#pragma unroll
            for (int g = 0; g < 8; ++g) acc += part[g * 256 + b * 64 + d];
            const float* tr = tape + b * NSLOT * 65 + d;
            const float* cf = coef + b * 32;
#pragma unroll 8
            for (int n = 0; n < NSLOT; ++n) acc += cf[n] * tr[n * 65];
            float h = tanhf(acc);
            __stcs(&out_hseq[((size_t)(b0 + b) * TSTEPS + t) * DIMN + dbase + d], h);
            uint32_t off = (unsigned)(p * 2048 + rank * 256 + b * 64 + d) * 4u;
#pragma unroll
            for (int peer = 0; peer < RANKS; ++peer)
                sts_cluster_f32(mapa_rank(a_xwn + off, peer), h);
        }
        __syncthreads();
        if (tid == 0) {
#pragma unroll
            for (int peer = 0; peer < RANKS; ++peer)
                mbar_arrive_cl(mapa_rank(a_mb + 8, peer));
        }
        mbar_wait_parity_cl(a_mb + 8, (uint32_t)p);

        // phase 4: W_write GEMV partials on full wnew, reduce -> local wvec chunk
        gemv_part(g_WwP, xwn_new, part, wid, lane, dbase);
        __syncthreads();
        if (tid < 256) {
            int b = tid >> 6, d = tid & 63;
            float acc = 0.f;
#pragma unroll
            for (int g = 0; g < 8; ++g) acc += part[g * 256 + b * 64 + d];
            wvec[b * 64 + d] = acc;
        }
        __syncthreads();

        // phase 5: partial write-scores, push
        if (wid < BPC)
            scores_push(tape, wvec + wid * 64, wid, lane, a_xws, p, rank);
        __syncthreads();
        if (tid == 0) {
#pragma unroll
            for (int peer = 0; peer < RANKS; ++peer)
                mbar_arrive_cl(mapa_rank(a_mb + 16, peer));
        }
        mbar_wait_parity_cl(a_mb + 16, (uint32_t)p);

        // phase 6: reduce + entmax (beta)
        if (wid < BPC) {
            const float* base = xws + p * 1024 + wid * 32 + lane;
            float s = 0.f;
#pragma unroll
            for (int sl = 0; sl < RANKS; ++sl) s += base[sl * 128];
            coef[wid * 32 + lane] = entmax_coef(s, sortb + wid * 32, lane);
        }
        __syncthreads();

        // phase 7: convex tape update
        if (tid < 256) {
            int b = tid >> 6, d = tid & 63;
            float wv = wvec[b * 64 + d];
            float* tr = tape + b * NSLOT * 65 + d;
            const float* cf = coef + b * 32;
#pragma unroll 8
            for (int n = 0; n < NSLOT; ++n) {
                float bt = cf[n];
                tr[n * 65] = tr[n * 65] * (1.f - bt) + bt * wv;
            }
        }
        __syncthreads();
    }

    // final outputs
    for (int i = tid; i < BPC * NSLOT * DCH; i += 512) {
        int b = i / (NSLOT * DCH);
        int r = i % (NSLOT * DCH);
        int n = r / DCH;
        int d = r % DCH;
        out_tape[((size_t)(b0 + b) * NSLOT + n) * DIMN + dbase + d] =
            tape[(b * NSLOT + n) * 65 + d];
    }
    if (tid < 256) {
        int b = tid >> 6, d = tid & 63;
        // final work = wnew(T-1), parity (T-1)&1 == 1, my own chunk slot
        out_hlast[(size_t)(b0 + b) * DIMN + dbase + d] =
            xwn[2048 + rank * 256 + b * 64 + d];
    }
    cluster_sync_();
}

// ---------------- launch ----------------
extern "C" void kernel_launch(void* const* d_in, const int* in_sizes, int n_in,
                              void* d_out, int out_size) {
    const float* x     = (const float*)d_in[0];  // [B,T,D]
    const float* tape0 = (const float*)d_in[1];  // [B,N,D]
    const float* work0 = (const float*)d_in[2];  // [B,D]
    const float* Wh    = (const float*)d_in[3];  // [D,D]
    const float* Wx    = (const float*)d_in[4];  // [D,D]
    const float* bh    = (const float*)d_in[5];  // [D]
    const float* Ww    = (const float*)d_in[6];  // [D,D]

    float* out       = (float*)d_out;
    float* out_hseq  = out;
    float* out_tape  = out + (size_t)BATCH * TSTEPS * DIMN;
    float* out_hlast = out_tape + (size_t)BATCH * NSLOT * DIMN;

    pack_weights<<<(DIMN * DIMN + 511) / 512, 512>>>(Wh, Ww);

    dim3 ggrid(DIMN / 64, (BATCH * TSTEPS) / 128);
    gemm_pre<<<ggrid, 256>>>(x, Wx, bh);

    const int smem_bytes = 19072 * 4 + 32;  // arrays + mbarriers
    cudaFuncSetAttribute(recur2, cudaFuncAttributeMaxDynamicSharedMemorySize, smem_bytes);
    recur2<<<BATCH / BPC * RANKS, 512, smem_bytes>>>(tape0, work0, out_hseq, out_tape, out_hlast);
}